// round 16
// baseline (speedup 1.0000x reference)
#include <cuda_runtime.h>
#include <cuda_fp16.h>
#include <cstdint>
#include <math.h>

#define T_STEPS 1024
#define A_DIM   64
#define H_DIM   2048
#define G3      (3 * H_DIM)
#define WSLOTS  16                         // per-CTA warp slots for GRU weights in SMEM
#define SMV_BYTES (H_DIM * 2)              // staged fp16 vector (half)
#define DSM_BYTES (SMV_BYTES + WSLOTS * 3 * H_DIM * 2)   // 4096 + 196608 = 200704

// ---------------- persistent device scratch (no allocations allowed) ----------------
__device__ float    g_GI[T_STEPS * G3];       // precomputed input gates (incl. b_ih)
__device__ float    g_S [T_STEPS * H_DIM];    // s2 per step for deferred mean/std GEMMs
// tagged exchange buffers: .x = fp32 value bits, .y = tag (monotonic per replay)
__device__ uint2    g_hT [H_DIM];             // h carries tag t  (reset: tag 0)
__device__ uint2    g_s0T[H_DIM];             // s0 carries tag t+1
__device__ uint2    g_s1T[H_DIM];             // s1 carries tag t+1

// ---------------- helpers ----------------
__device__ __forceinline__ float sigmoidf_(float x) { return 1.0f / (1.0f + expf(-x)); }
__device__ __forceinline__ float eluf_(float x)     { return x > 0.0f ? x : expm1f(x); }

__device__ __forceinline__ uint4 pack8h(float4 a, float4 b)
{
    __half2 h0 = __floats2half2_rn(a.x, a.y);
    __half2 h1 = __floats2half2_rn(a.z, a.w);
    __half2 h2 = __floats2half2_rn(b.x, b.y);
    __half2 h3 = __floats2half2_rn(b.z, b.w);
    uint4 u;
    u.x = *reinterpret_cast<uint32_t*>(&h0);
    u.y = *reinterpret_cast<uint32_t*>(&h1);
    u.z = *reinterpret_cast<uint32_t*>(&h2);
    u.w = *reinterpret_cast<uint32_t*>(&h3);
    return u;
}

// dot of 8 packed fp16 weights with 8 packed fp16 vector values, accumulated
// into fp32 (chain length 4 per half-lane, flushed immediately)
__device__ __forceinline__ float dot8f(uint4 w, uint4 s)
{
    const __half2* wh = reinterpret_cast<const __half2*>(&w);
    const __half2* sh = reinterpret_cast<const __half2*>(&s);
    __half2 c = __hmul2(wh[0], sh[0]);
    c = __hfma2(wh[1], sh[1], c);
    c = __hfma2(wh[2], sh[2], c);
    c = __hfma2(wh[3], sh[3], c);
    float2 f = __half22float2(c);
    return f.x + f.y;
}

// Poll two (value, tag) pairs (16B) until both tags match.
__device__ __forceinline__ uint4 poll4(const uint2* addr, unsigned tag)
{
    const uint4* p = reinterpret_cast<const uint4*>(addr);
    uint4 v;
    int spins = 0;
    for (;;) {
        asm volatile("ld.volatile.global.v4.u32 {%0,%1,%2,%3}, [%4];"
                     : "=r"(v.x), "=r"(v.y), "=r"(v.z), "=r"(v.w)
                     : "l"(p) : "memory");
        if (v.y == tag && v.w == tag) return v;
        if (++spins > 2) __nanosleep(40);
    }
}

// ---------------- init kernel (each replay: resets tags + initial state) ------
__global__ void reset_kernel(const float* __restrict__ state)
{
    int i = blockIdx.x * blockDim.x + threadIdx.x;
    if (i < H_DIM) {
        g_hT [i] = make_uint2(__float_as_uint(state[i]), 0u);
        g_s0T[i] = make_uint2(0u, 0u);
        g_s1T[i] = make_uint2(0u, 0u);
    }
}

// ---------------- C[m][n] = act( sum_k A[m][k]*B[n][k] + bias[n] ) ----------
// BM=128, BN=64, BK=16, 256 threads, 8x4 micro-tile. All dims divide evenly.
__global__ void __launch_bounds__(256) gemm_bias_act(
    const float* __restrict__ A, const float* __restrict__ B,
    const float* __restrict__ bias, float* __restrict__ C,
    int M, int N, int K, int act)
{
    __shared__ __align__(16) float As[16][132];
    __shared__ __align__(16) float Bs[16][68];

    const int tid = threadIdx.x;
    const int tx  = tid & 15;
    const int ty  = tid >> 4;
    const int n0  = blockIdx.x * 64;
    const int m0  = blockIdx.y * 128;

    float c[8][4] = {};

    for (int k0 = 0; k0 < K; k0 += 16) {
        #pragma unroll
        for (int idx = tid; idx < 128 * 16; idx += 256) {
            int m  = idx >> 4;
            int kk = idx & 15;
            As[kk][m] = A[(size_t)(m0 + m) * K + k0 + kk];
        }
        #pragma unroll
        for (int idx = tid; idx < 64 * 16; idx += 256) {
            int m  = idx >> 4;
            int kk = idx & 15;
            Bs[kk][m] = B[(size_t)(n0 + m) * K + k0 + kk];
        }
        __syncthreads();

        #pragma unroll
        for (int kk = 0; kk < 16; ++kk) {
            float4 b4 = *reinterpret_cast<const float4*>(&Bs[kk][tx * 4]);
            float4 a0 = *reinterpret_cast<const float4*>(&As[kk][ty * 8]);
            float4 a1 = *reinterpret_cast<const float4*>(&As[kk][ty * 8 + 4]);
            c[0][0] += a0.x * b4.x; c[0][1] += a0.x * b4.y; c[0][2] += a0.x * b4.z; c[0][3] += a0.x * b4.w;
            c[1][0] += a0.y * b4.x; c[1][1] += a0.y * b4.y; c[1][2] += a0.y * b4.z; c[1][3] += a0.y * b4.w;
            c[2][0] += a0.z * b4.x; c[2][1] += a0.z * b4.y; c[2][2] += a0.z * b4.z; c[2][3] += a0.z * b4.w;
            c[3][0] += a0.w * b4.x; c[3][1] += a0.w * b4.y; c[3][2] += a0.w * b4.z; c[3][3] += a0.w * b4.w;
            c[4][0] += a1.x * b4.x; c[4][1] += a1.x * b4.y; c[4][2] += a1.x * b4.z; c[4][3] += a1.x * b4.w;
            c[5][0] += a1.y * b4.x; c[5][1] += a1.y * b4.y; c[5][2] += a1.y * b4.z; c[5][3] += a1.y * b4.w;
            c[6][0] += a1.z * b4.x; c[6][1] += a1.z * b4.y; c[6][2] += a1.z * b4.z; c[6][3] += a1.z * b4.w;
            c[7][0] += a1.w * b4.x; c[7][1] += a1.w * b4.y; c[7][2] += a1.w * b4.z; c[7][3] += a1.w * b4.w;
        }
        __syncthreads();
    }

    #pragma unroll
    for (int i = 0; i < 8; ++i) {
        #pragma unroll
        for (int j = 0; j < 4; ++j) {
            int m = m0 + ty * 8 + i;
            int n = n0 + tx * 4 + j;
            float v = c[i][j] + bias[n];
            if (act == 1) v = (v > 20.0f) ? v : log1pf(expf(v));   // softplus
            C[(size_t)m * N + n] = v;
        }
    }
}

// ---------------- persistent recurrent kernel: data-flow sync, no grid barrier -----
// grid = NB (= #SMs), 512 threads, 1 CTA/SM (200.7 KB dynamic SMEM forces it).
// GRU weights in SMEM (fp16, per-warp slot); fc1/fc2 rows in registers (fp16).
// Phase outputs are (fp32 value, tag) pairs; consumers poll tags directly.
__global__ void __launch_bounds__(512, 1) recurrent_kernel(
    const float* __restrict__ Whh,  const float* __restrict__ bhh,
    const float* __restrict__ fc1w, const float* __restrict__ fc1b,
    const float* __restrict__ fc2w, const float* __restrict__ fc2b,
    int NB)
{
    extern __shared__ __align__(16) char dsm[];
    __half* smh  = reinterpret_cast<__half*>(dsm);               // [2048] staged fp16 vector
    __half* wg   = reinterpret_cast<__half*>(dsm + SMV_BYTES);   // [WSLOTS][3][2048]

    const int tid  = threadIdx.x;
    const int bid  = blockIdx.x;
    const int wid  = tid >> 5;
    const int lane = tid & 31;
    (void)NB;

    const int  row  = wid * NB + bid;      // this warp's output row in every phase
    const bool live = (row < H_DIM);
    const int  kb   = lane * 8;            // per-lane K base (8 halfs per uint4)

    __half* wrow = wg + (size_t)wid * 3 * H_DIM;

    // ---------- one-time: weights -> SMEM (GRU) and registers (fc1, fc2) ----------
    uint4 rf1[8], rf2[8];
    float b_r = 0.f, b_z = 0.f, b_n = 0.f, b_f1 = 0.f, b_f2 = 0.f;
    if (live) {
        #pragma unroll
        for (int g = 0; g < 3; ++g) {
            const float* src = Whh + (size_t)(row + g * H_DIM) * H_DIM;
            #pragma unroll
            for (int it = 0; it < 8; ++it) {
                const int k = kb + it * 256;
                float4 a = *reinterpret_cast<const float4*>(src + k);
                float4 b = *reinterpret_cast<const float4*>(src + k + 4);
                *reinterpret_cast<uint4*>(wrow + g * H_DIM + k) = pack8h(a, b);
            }
        }
        const float* s1p = fc1w + (size_t)row * H_DIM;
        const float* s2p = fc2w + (size_t)row * H_DIM;
        #pragma unroll
        for (int it = 0; it < 8; ++it) {
            const int k = kb + it * 256;
            float4 a1 = *reinterpret_cast<const float4*>(s1p + k);
            float4 b1 = *reinterpret_cast<const float4*>(s1p + k + 4);
            float4 a2 = *reinterpret_cast<const float4*>(s2p + k);
            float4 b2 = *reinterpret_cast<const float4*>(s2p + k + 4);
            rf1[it] = pack8h(a1, b1);
            rf2[it] = pack8h(a2, b2);
        }
        b_r  = bhh[row];
        b_z  = bhh[row + H_DIM];
        b_n  = bhh[row + 2 * H_DIM];
        b_f1 = fc1b[row];
        b_f2 = fc2b[row];
    } else {
        #pragma unroll
        for (int it = 0; it < 8; ++it) { rf1[it] = make_uint4(0,0,0,0); rf2[it] = make_uint4(0,0,0,0); }
    }

    for (int t = 0; t < T_STEPS; ++t) {
        const unsigned tag_in  = (unsigned)t;       // h produced by previous step
        const unsigned tag_out = (unsigned)t + 1u;  // everything produced this step

        // ---------- P1 staging: poll h (tag t) -> smh as fp16 ----------
        {
            uint4 a = poll4(g_hT + tid * 4,     tag_in);
            uint4 b = poll4(g_hT + tid * 4 + 2, tag_in);
            __half2 p0 = __floats2half2_rn(__uint_as_float(a.x), __uint_as_float(a.z));
            __half2 p1 = __floats2half2_rn(__uint_as_float(b.x), __uint_as_float(b.z));
            uint2 st;
            st.x = *reinterpret_cast<uint32_t*>(&p0);
            st.y = *reinterpret_cast<uint32_t*>(&p1);
            *reinterpret_cast<uint2*>(smh + tid * 4) = st;
        }
        __syncthreads();

        // ---------- P1: GRU cell ----------
        if (live) {
            float ir = 0.f, iz = 0.f, in_ = 0.f, hp = 0.f;
            if (lane == 0) {
                const float* gi = g_GI + (size_t)t * G3;
                ir  = __ldcg(gi + row);
                iz  = __ldcg(gi + row + H_DIM);
                in_ = __ldcg(gi + row + 2 * H_DIM);
                uint2 hv = __ldcg(&g_hT[row]);      // tag==t guaranteed (staging saw it)
                hp = __uint_as_float(hv.x);
            }
            float a0 = 0.f, a1 = 0.f, a2 = 0.f;
            #pragma unroll 2
            for (int it = 0; it < 8; ++it) {
                const int k = kb + it * 256;
                uint4 sv = *reinterpret_cast<const uint4*>(smh + k);
                uint4 u0 = *reinterpret_cast<const uint4*>(wrow + k);
                uint4 u1 = *reinterpret_cast<const uint4*>(wrow + H_DIM + k);
                uint4 u2 = *reinterpret_cast<const uint4*>(wrow + 2 * H_DIM + k);
                a0 += dot8f(u0, sv);
                a1 += dot8f(u1, sv);
                a2 += dot8f(u2, sv);
            }
            #pragma unroll
            for (int o = 16; o > 0; o >>= 1) {
                a0 += __shfl_xor_sync(0xffffffffu, a0, o);
                a1 += __shfl_xor_sync(0xffffffffu, a1, o);
                a2 += __shfl_xor_sync(0xffffffffu, a2, o);
            }
            if (lane == 0) {
                float r  = sigmoidf_(ir + a0 + b_r);
                float z  = sigmoidf_(iz + a1 + b_z);
                float n  = tanhf(in_ + r * (a2 + b_n));
                float hnew = (1.0f - z) * n + z * hp;
                uint2 o2;
                o2.x = __float_as_uint(eluf_(hnew));
                o2.y = tag_out;
                __stcg(&g_s0T[row], o2);
            }
        }
        __syncthreads();   // protect smh before restaging

        // ---------- P2 staging: poll s0 (tag t+1) ----------
        {
            uint4 a = poll4(g_s0T + tid * 4,     tag_out);
            uint4 b = poll4(g_s0T + tid * 4 + 2, tag_out);
            __half2 p0 = __floats2half2_rn(__uint_as_float(a.x), __uint_as_float(a.z));
            __half2 p1 = __floats2half2_rn(__uint_as_float(b.x), __uint_as_float(b.z));
            uint2 st;
            st.x = *reinterpret_cast<uint32_t*>(&p0);
            st.y = *reinterpret_cast<uint32_t*>(&p1);
            *reinterpret_cast<uint2*>(smh + tid * 4) = st;
        }
        __syncthreads();

        // ---------- P2: fc1 ----------
        if (live) {
            float a = 0.f;
            #pragma unroll
            for (int it = 0; it < 8; ++it) {
                const int k = kb + it * 256;
                uint4 sv = *reinterpret_cast<const uint4*>(smh + k);
                a += dot8f(rf1[it], sv);
            }
            #pragma unroll
            for (int o = 16; o > 0; o >>= 1) a += __shfl_xor_sync(0xffffffffu, a, o);
            if (lane == 0) {
                uint2 o2;
                o2.x = __float_as_uint(eluf_(a + b_f1));
                o2.y = tag_out;
                __stcg(&g_s1T[row], o2);
            }
        }
        __syncthreads();

        // ---------- P3 staging: poll s1 (tag t+1) ----------
        {
            uint4 a = poll4(g_s1T + tid * 4,     tag_out);
            uint4 b = poll4(g_s1T + tid * 4 + 2, tag_out);
            __half2 p0 = __floats2half2_rn(__uint_as_float(a.x), __uint_as_float(a.z));
            __half2 p1 = __floats2half2_rn(__uint_as_float(b.x), __uint_as_float(b.z));
            uint2 st;
            st.x = *reinterpret_cast<uint32_t*>(&p0);
            st.y = *reinterpret_cast<uint32_t*>(&p1);
            *reinterpret_cast<uint2*>(smh + tid * 4) = st;
        }
        __syncthreads();

        // ---------- P3: fc2 (result is next h and S[t]) ----------
        if (live) {
            float a = 0.f;
            #pragma unroll
            for (int it = 0; it < 8; ++it) {
                const int k = kb + it * 256;
                uint4 sv = *reinterpret_cast<const uint4*>(smh + k);
                a += dot8f(rf2[it], sv);
            }
            #pragma unroll
            for (int o = 16; o > 0; o >>= 1) a += __shfl_xor_sync(0xffffffffu, a, o);
            if (lane == 0) {
                float s2 = eluf_(a + b_f2);
                uint2 o2;
                o2.x = __float_as_uint(s2);
                o2.y = tag_out;
                __stcg(&g_hT[row], o2);
                g_S[(size_t)t * H_DIM + row] = s2;
            }
        }
        __syncthreads();
    }
}

// ---------------- launch ----------------
extern "C" void kernel_launch(void* const* d_in, const int* in_sizes, int n_in,
                              void* d_out, int out_size)
{
    (void)n_in; (void)out_size;

    const float *actions, *state, *Wih, *Whh, *bih, *bhh;
    const float *fc1w, *fc1b, *fc2w, *fc2b, *meanw, *meanb, *stdw, *stdb;

    if (in_sizes[0] == T_STEPS * A_DIM) {
        // declaration order
        actions = (const float*)d_in[0];  state = (const float*)d_in[1];
        Wih     = (const float*)d_in[2];  Whh   = (const float*)d_in[3];
        bih     = (const float*)d_in[4];  bhh   = (const float*)d_in[5];
        fc1w    = (const float*)d_in[6];  fc1b  = (const float*)d_in[7];
        fc2w    = (const float*)d_in[8];  fc2b  = (const float*)d_in[9];
        meanw   = (const float*)d_in[10]; meanb = (const float*)d_in[11];
        stdw    = (const float*)d_in[12]; stdb  = (const float*)d_in[13];
    } else {
        // alphabetical: W_hh, W_ih, actions, b_hh, b_ih, fc1_b, fc1_w, fc2_b,
        //               fc2_w, mean_b, mean_w, state, std_b, std_w
        Whh     = (const float*)d_in[0];  Wih   = (const float*)d_in[1];
        actions = (const float*)d_in[2];  bhh   = (const float*)d_in[3];
        bih     = (const float*)d_in[4];  fc1b  = (const float*)d_in[5];
        fc1w    = (const float*)d_in[6];  fc2b  = (const float*)d_in[7];
        fc2w    = (const float*)d_in[8];  meanb = (const float*)d_in[9];
        meanw   = (const float*)d_in[10]; state = (const float*)d_in[11];
        stdb    = (const float*)d_in[12]; stdw  = (const float*)d_in[13];
    }
    float* out = (float*)d_out;

    int dev = 0;
    cudaGetDevice(&dev);
    int nsm = 148;
    cudaDeviceGetAttribute(&nsm, cudaDevAttrMultiProcessorCount, dev);
    if (nsm < 128) nsm = 128;         // mapping needs 16*NB >= 2048

    float* gi = nullptr;  cudaGetSymbolAddress((void**)&gi, g_GI);
    float* S  = nullptr;  cudaGetSymbolAddress((void**)&S,  g_S);

    static bool attr_done = false;
    if (!attr_done) {
        cudaFuncSetAttribute(recurrent_kernel,
                             cudaFuncAttributeMaxDynamicSharedMemorySize, DSM_BYTES);
        attr_done = true;
    }

    // 1) reset tags + initial state (every replay)
    reset_kernel<<<2, 1024>>>(state);

    // 2) precompute input gates: GI[t][g] = actions[t] . W_ih[g] + b_ih[g]
    {
        dim3 grid(G3 / 64, T_STEPS / 128);
        gemm_bias_act<<<grid, 256>>>(actions, Wih, bih, gi, T_STEPS, G3, A_DIM, 0);
    }

    // 3) sequential recurrence (persistent, SM-resident weights, data-flow sync)
    recurrent_kernel<<<nsm, 512, DSM_BYTES>>>(Whh, bhh, fc1w, fc1b, fc2w, fc2b, nsm);

    // 4) deferred heads: means (identity) and stds (softplus)
    {
        dim3 grid(H_DIM / 64, T_STEPS / 128);
        gemm_bias_act<<<grid, 256>>>(S, meanw, meanb, out, T_STEPS, H_DIM, H_DIM, 0);
        gemm_bias_act<<<grid, 256>>>(S, stdw,  stdb,  out + (size_t)T_STEPS * H_DIM,
                                     T_STEPS, H_DIM, H_DIM, 1);
    }
}

// round 17
// speedup vs baseline: 1.0105x; 1.0105x over previous
#include <cuda_runtime.h>
#include <cuda_fp16.h>
#include <cstdint>
#include <math.h>

#define T_STEPS 1024
#define A_DIM   64
#define H_DIM   2048
#define G3      (3 * H_DIM)
#define WSLOTS  16                         // per-CTA warp slots for GRU weights in SMEM
#define SMV_BYTES (H_DIM * 2)              // staged fp16 vector (half)
#define DSM_BYTES (SMV_BYTES + WSLOTS * 3 * H_DIM * 2)   // 4096 + 196608 = 200704

// ---------------- persistent device scratch (no allocations allowed) ----------------
__device__ float    g_GI[T_STEPS * G3];       // precomputed input gates (incl. b_ih)
__device__ float    g_S [T_STEPS * H_DIM];    // s2 per step for deferred mean/std GEMMs
// tagged exchange buffers: .x = fp32 value bits, .y = tag (monotonic per replay)
__device__ uint2    g_hT [H_DIM];             // h carries tag t  (reset: tag 0)
__device__ uint2    g_s0T[H_DIM];             // s0 carries tag t+1
__device__ uint2    g_s1T[H_DIM];             // s1 carries tag t+1

// ---------------- helpers ----------------
__device__ __forceinline__ float sigmoidf_(float x) { return 1.0f / (1.0f + expf(-x)); }
__device__ __forceinline__ float eluf_(float x)     { return x > 0.0f ? x : expm1f(x); }

__device__ __forceinline__ uint4 pack8h(float4 a, float4 b)
{
    __half2 h0 = __floats2half2_rn(a.x, a.y);
    __half2 h1 = __floats2half2_rn(a.z, a.w);
    __half2 h2 = __floats2half2_rn(b.x, b.y);
    __half2 h3 = __floats2half2_rn(b.z, b.w);
    uint4 u;
    u.x = *reinterpret_cast<uint32_t*>(&h0);
    u.y = *reinterpret_cast<uint32_t*>(&h1);
    u.z = *reinterpret_cast<uint32_t*>(&h2);
    u.w = *reinterpret_cast<uint32_t*>(&h3);
    return u;
}

// dot of 8 packed fp16 weights with 8 packed fp16 vector values, accumulated
// into fp32 (chain length 4 per half-lane, flushed immediately)
__device__ __forceinline__ float dot8f(uint4 w, uint4 s)
{
    const __half2* wh = reinterpret_cast<const __half2*>(&w);
    const __half2* sh = reinterpret_cast<const __half2*>(&s);
    __half2 c = __hmul2(wh[0], sh[0]);
    c = __hfma2(wh[1], sh[1], c);
    c = __hfma2(wh[2], sh[2], c);
    c = __hfma2(wh[3], sh[3], c);
    float2 f = __half22float2(c);
    return f.x + f.y;
}

// Poll two (value, tag) pairs (16B) until both tags match.
__device__ __forceinline__ uint4 poll4(const uint2* addr, unsigned tag)
{
    const uint4* p = reinterpret_cast<const uint4*>(addr);
    uint4 v;
    int spins = 0;
    for (;;) {
        asm volatile("ld.volatile.global.v4.u32 {%0,%1,%2,%3}, [%4];"
                     : "=r"(v.x), "=r"(v.y), "=r"(v.z), "=r"(v.w)
                     : "l"(p) : "memory");
        if (v.y == tag && v.w == tag) return v;
        if (++spins > 2) __nanosleep(40);
    }
}

// ---------------- init kernel (each replay: resets tags + initial state) ------
__global__ void reset_kernel(const float* __restrict__ state)
{
    int i = blockIdx.x * blockDim.x + threadIdx.x;
    if (i < H_DIM) {
        g_hT [i] = make_uint2(__float_as_uint(state[i]), 0u);
        g_s0T[i] = make_uint2(0u, 0u);
        g_s1T[i] = make_uint2(0u, 0u);
    }
}

// ---------------- C[m][n] = act( sum_k A[m][k]*B[n][k] + bias[n] ) ----------
// BM=128, BN=64, BK=16, 256 threads, 8x4 micro-tile. All dims divide evenly.
__global__ void __launch_bounds__(256) gemm_bias_act(
    const float* __restrict__ A, const float* __restrict__ B,
    const float* __restrict__ bias, float* __restrict__ C,
    int M, int N, int K, int act)
{
    __shared__ __align__(16) float As[16][132];
    __shared__ __align__(16) float Bs[16][68];

    const int tid = threadIdx.x;
    const int tx  = tid & 15;
    const int ty  = tid >> 4;
    const int n0  = blockIdx.x * 64;
    const int m0  = blockIdx.y * 128;

    float c[8][4] = {};

    for (int k0 = 0; k0 < K; k0 += 16) {
        #pragma unroll
        for (int idx = tid; idx < 128 * 16; idx += 256) {
            int m  = idx >> 4;
            int kk = idx & 15;
            As[kk][m] = A[(size_t)(m0 + m) * K + k0 + kk];
        }
        #pragma unroll
        for (int idx = tid; idx < 64 * 16; idx += 256) {
            int m  = idx >> 4;
            int kk = idx & 15;
            Bs[kk][m] = B[(size_t)(n0 + m) * K + k0 + kk];
        }
        __syncthreads();

        #pragma unroll
        for (int kk = 0; kk < 16; ++kk) {
            float4 b4 = *reinterpret_cast<const float4*>(&Bs[kk][tx * 4]);
            float4 a0 = *reinterpret_cast<const float4*>(&As[kk][ty * 8]);
            float4 a1 = *reinterpret_cast<const float4*>(&As[kk][ty * 8 + 4]);
            c[0][0] += a0.x * b4.x; c[0][1] += a0.x * b4.y; c[0][2] += a0.x * b4.z; c[0][3] += a0.x * b4.w;
            c[1][0] += a0.y * b4.x; c[1][1] += a0.y * b4.y; c[1][2] += a0.y * b4.z; c[1][3] += a0.y * b4.w;
            c[2][0] += a0.z * b4.x; c[2][1] += a0.z * b4.y; c[2][2] += a0.z * b4.z; c[2][3] += a0.z * b4.w;
            c[3][0] += a0.w * b4.x; c[3][1] += a0.w * b4.y; c[3][2] += a0.w * b4.z; c[3][3] += a0.w * b4.w;
            c[4][0] += a1.x * b4.x; c[4][1] += a1.x * b4.y; c[4][2] += a1.x * b4.z; c[4][3] += a1.x * b4.w;
            c[5][0] += a1.y * b4.x; c[5][1] += a1.y * b4.y; c[5][2] += a1.y * b4.z; c[5][3] += a1.y * b4.w;
            c[6][0] += a1.z * b4.x; c[6][1] += a1.z * b4.y; c[6][2] += a1.z * b4.z; c[6][3] += a1.z * b4.w;
            c[7][0] += a1.w * b4.x; c[7][1] += a1.w * b4.y; c[7][2] += a1.w * b4.z; c[7][3] += a1.w * b4.w;
        }
        __syncthreads();
    }

    #pragma unroll
    for (int i = 0; i < 8; ++i) {
        #pragma unroll
        for (int j = 0; j < 4; ++j) {
            int m = m0 + ty * 8 + i;
            int n = n0 + tx * 4 + j;
            float v = c[i][j] + bias[n];
            if (act == 1) v = (v > 20.0f) ? v : log1pf(expf(v));   // softplus
            C[(size_t)m * N + n] = v;
        }
    }
}

// ---------------- persistent recurrent kernel: data-flow sync, no grid barrier -----
// grid = NB (= #SMs), 512 threads, 1 CTA/SM (200.7 KB dynamic SMEM forces it).
// GRU weights in SMEM (fp16, per-warp slot); fc1/fc2 rows in registers (fp16).
// Phase outputs are (fp32 value, tag) pairs; consumers poll tags directly.
__global__ void __launch_bounds__(512, 1) recurrent_kernel(
    const float* __restrict__ Whh,  const float* __restrict__ bhh,
    const float* __restrict__ fc1w, const float* __restrict__ fc1b,
    const float* __restrict__ fc2w, const float* __restrict__ fc2b,
    int NB)
{
    extern __shared__ __align__(16) char dsm[];
    __half* smh  = reinterpret_cast<__half*>(dsm);               // [2048] staged fp16 vector
    __half* wg   = reinterpret_cast<__half*>(dsm + SMV_BYTES);   // [WSLOTS][3][2048]

    const int tid  = threadIdx.x;
    const int bid  = blockIdx.x;
    const int wid  = tid >> 5;
    const int lane = tid & 31;
    (void)NB;

    const int  row  = wid * NB + bid;      // this warp's output row in every phase
    const bool live = (row < H_DIM);
    const int  kb   = lane * 8;            // per-lane K base (8 halfs per uint4)

    __half* wrow = wg + (size_t)wid * 3 * H_DIM;

    // ---------- one-time: weights -> SMEM (GRU) and registers (fc1, fc2) ----------
    uint4 rf1[8], rf2[8];
    float b_r = 0.f, b_z = 0.f, b_n = 0.f, b_f1 = 0.f, b_f2 = 0.f;
    if (live) {
        #pragma unroll
        for (int g = 0; g < 3; ++g) {
            const float* src = Whh + (size_t)(row + g * H_DIM) * H_DIM;
            #pragma unroll
            for (int it = 0; it < 8; ++it) {
                const int k = kb + it * 256;
                float4 a = *reinterpret_cast<const float4*>(src + k);
                float4 b = *reinterpret_cast<const float4*>(src + k + 4);
                *reinterpret_cast<uint4*>(wrow + g * H_DIM + k) = pack8h(a, b);
            }
        }
        const float* s1p = fc1w + (size_t)row * H_DIM;
        const float* s2p = fc2w + (size_t)row * H_DIM;
        #pragma unroll
        for (int it = 0; it < 8; ++it) {
            const int k = kb + it * 256;
            float4 a1 = *reinterpret_cast<const float4*>(s1p + k);
            float4 b1 = *reinterpret_cast<const float4*>(s1p + k + 4);
            float4 a2 = *reinterpret_cast<const float4*>(s2p + k);
            float4 b2 = *reinterpret_cast<const float4*>(s2p + k + 4);
            rf1[it] = pack8h(a1, b1);
            rf2[it] = pack8h(a2, b2);
        }
        b_r  = bhh[row];
        b_z  = bhh[row + H_DIM];
        b_n  = bhh[row + 2 * H_DIM];
        b_f1 = fc1b[row];
        b_f2 = fc2b[row];
    } else {
        #pragma unroll
        for (int it = 0; it < 8; ++it) { rf1[it] = make_uint4(0,0,0,0); rf2[it] = make_uint4(0,0,0,0); }
    }

    for (int t = 0; t < T_STEPS; ++t) {
        const unsigned tag_in  = (unsigned)t;       // h produced by previous step
        const unsigned tag_out = (unsigned)t + 1u;  // everything produced this step

        // ---------- P1 staging: poll h (tag t) -> smh as fp16 ----------
        {
            uint4 a = poll4(g_hT + tid * 4,     tag_in);
            uint4 b = poll4(g_hT + tid * 4 + 2, tag_in);
            __half2 p0 = __floats2half2_rn(__uint_as_float(a.x), __uint_as_float(a.z));
            __half2 p1 = __floats2half2_rn(__uint_as_float(b.x), __uint_as_float(b.z));
            uint2 st;
            st.x = *reinterpret_cast<uint32_t*>(&p0);
            st.y = *reinterpret_cast<uint32_t*>(&p1);
            *reinterpret_cast<uint2*>(smh + tid * 4) = st;
        }
        __syncthreads();

        // ---------- P1: GRU cell ----------
        if (live) {
            float ir = 0.f, iz = 0.f, in_ = 0.f, hp = 0.f;
            if (lane == 0) {
                const float* gi = g_GI + (size_t)t * G3;
                ir  = __ldcg(gi + row);
                iz  = __ldcg(gi + row + H_DIM);
                in_ = __ldcg(gi + row + 2 * H_DIM);
                uint2 hv = __ldcg(&g_hT[row]);      // tag==t guaranteed (staging saw it)
                hp = __uint_as_float(hv.x);
            }
            float a0 = 0.f, a1 = 0.f, a2 = 0.f;
            #pragma unroll 2
            for (int it = 0; it < 8; ++it) {
                const int k = kb + it * 256;
                uint4 sv = *reinterpret_cast<const uint4*>(smh + k);
                uint4 u0 = *reinterpret_cast<const uint4*>(wrow + k);
                uint4 u1 = *reinterpret_cast<const uint4*>(wrow + H_DIM + k);
                uint4 u2 = *reinterpret_cast<const uint4*>(wrow + 2 * H_DIM + k);
                a0 += dot8f(u0, sv);
                a1 += dot8f(u1, sv);
                a2 += dot8f(u2, sv);
            }
            #pragma unroll
            for (int o = 16; o > 0; o >>= 1) {
                a0 += __shfl_xor_sync(0xffffffffu, a0, o);
                a1 += __shfl_xor_sync(0xffffffffu, a1, o);
                a2 += __shfl_xor_sync(0xffffffffu, a2, o);
            }
            if (lane == 0) {
                float r  = sigmoidf_(ir + a0 + b_r);
                float z  = sigmoidf_(iz + a1 + b_z);
                float n  = tanhf(in_ + r * (a2 + b_n));
                float hnew = (1.0f - z) * n + z * hp;
                uint2 o2;
                o2.x = __float_as_uint(eluf_(hnew));
                o2.y = tag_out;
                __stcg(&g_s0T[row], o2);
            }
        }
        __syncthreads();   // protect smh before restaging

        // ---------- P2 staging: poll s0 (tag t+1) ----------
        {
            uint4 a = poll4(g_s0T + tid * 4,     tag_out);
            uint4 b = poll4(g_s0T + tid * 4 + 2, tag_out);
            __half2 p0 = __floats2half2_rn(__uint_as_float(a.x), __uint_as_float(a.z));
            __half2 p1 = __floats2half2_rn(__uint_as_float(b.x), __uint_as_float(b.z));
            uint2 st;
            st.x = *reinterpret_cast<uint32_t*>(&p0);
            st.y = *reinterpret_cast<uint32_t*>(&p1);
            *reinterpret_cast<uint2*>(smh + tid * 4) = st;
        }
        __syncthreads();

        // ---------- P2: fc1 ----------
        if (live) {
            float a = 0.f;
            #pragma unroll
            for (int it = 0; it < 8; ++it) {
                const int k = kb + it * 256;
                uint4 sv = *reinterpret_cast<const uint4*>(smh + k);
                a += dot8f(rf1[it], sv);
            }
            #pragma unroll
            for (int o = 16; o > 0; o >>= 1) a += __shfl_xor_sync(0xffffffffu, a, o);
            if (lane == 0) {
                uint2 o2;
                o2.x = __float_as_uint(eluf_(a + b_f1));
                o2.y = tag_out;
                __stcg(&g_s1T[row], o2);
            }
        }
        __syncthreads();

        // ---------- P3 staging: poll s1 (tag t+1) ----------
        {
            uint4 a = poll4(g_s1T + tid * 4,     tag_out);
            uint4 b = poll4(g_s1T + tid * 4 + 2, tag_out);
            __half2 p0 = __floats2half2_rn(__uint_as_float(a.x), __uint_as_float(a.z));
            __half2 p1 = __floats2half2_rn(__uint_as_float(b.x), __uint_as_float(b.z));
            uint2 st;
            st.x = *reinterpret_cast<uint32_t*>(&p0);
            st.y = *reinterpret_cast<uint32_t*>(&p1);
            *reinterpret_cast<uint2*>(smh + tid * 4) = st;
        }
        __syncthreads();

        // ---------- P3: fc2 (result is next h and S[t]) ----------
        if (live) {
            float a = 0.f;
            #pragma unroll
            for (int it = 0; it < 8; ++it) {
                const int k = kb + it * 256;
                uint4 sv = *reinterpret_cast<const uint4*>(smh + k);
                a += dot8f(rf2[it], sv);
            }
            #pragma unroll
            for (int o = 16; o > 0; o >>= 1) a += __shfl_xor_sync(0xffffffffu, a, o);
            if (lane == 0) {
                float s2 = eluf_(a + b_f2);
                uint2 o2;
                o2.x = __float_as_uint(s2);
                o2.y = tag_out;
                __stcg(&g_hT[row], o2);
                g_S[(size_t)t * H_DIM + row] = s2;
            }
        }
        __syncthreads();
    }
}

// ---------------- launch ----------------
extern "C" void kernel_launch(void* const* d_in, const int* in_sizes, int n_in,
                              void* d_out, int out_size)
{
    (void)n_in; (void)out_size;

    const float *actions, *state, *Wih, *Whh, *bih, *bhh;
    const float *fc1w, *fc1b, *fc2w, *fc2b, *meanw, *meanb, *stdw, *stdb;

    if (in_sizes[0] == T_STEPS * A_DIM) {
        // declaration order
        actions = (const float*)d_in[0];  state = (const float*)d_in[1];
        Wih     = (const float*)d_in[2];  Whh   = (const float*)d_in[3];
        bih     = (const float*)d_in[4];  bhh   = (const float*)d_in[5];
        fc1w    = (const float*)d_in[6];  fc1b  = (const float*)d_in[7];
        fc2w    = (const float*)d_in[8];  fc2b  = (const float*)d_in[9];
        meanw   = (const float*)d_in[10]; meanb = (const float*)d_in[11];
        stdw    = (const float*)d_in[12]; stdb  = (const float*)d_in[13];
    } else {
        // alphabetical: W_hh, W_ih, actions, b_hh, b_ih, fc1_b, fc1_w, fc2_b,
        //               fc2_w, mean_b, mean_w, state, std_b, std_w
        Whh     = (const float*)d_in[0];  Wih   = (const float*)d_in[1];
        actions = (const float*)d_in[2];  bhh   = (const float*)d_in[3];
        bih     = (const float*)d_in[4];  fc1b  = (const float*)d_in[5];
        fc1w    = (const float*)d_in[6];  fc2b  = (const float*)d_in[7];
        fc2w    = (const float*)d_in[8];  meanb = (const float*)d_in[9];
        meanw   = (const float*)d_in[10]; state = (const float*)d_in[11];
        stdb    = (const float*)d_in[12]; stdw  = (const float*)d_in[13];
    }
    float* out = (float*)d_out;

    int dev = 0;
    cudaGetDevice(&dev);
    int nsm = 148;
    cudaDeviceGetAttribute(&nsm, cudaDevAttrMultiProcessorCount, dev);
    if (nsm < 128) nsm = 128;         // mapping needs 16*NB >= 2048

    float* gi = nullptr;  cudaGetSymbolAddress((void**)&gi, g_GI);
    float* S  = nullptr;  cudaGetSymbolAddress((void**)&S,  g_S);

    static bool attr_done = false;
    if (!attr_done) {
        cudaFuncSetAttribute(recurrent_kernel,
                             cudaFuncAttributeMaxDynamicSharedMemorySize, DSM_BYTES);
        attr_done = true;
    }

    // 1) reset tags + initial state (every replay)
    reset_kernel<<<2, 1024>>>(state);

    // 2) precompute input gates: GI[t][g] = actions[t] . W_ih[g] + b_ih[g]
    {
        dim3 grid(G3 / 64, T_STEPS / 128);
        gemm_bias_act<<<grid, 256>>>(actions, Wih, bih, gi, T_STEPS, G3, A_DIM, 0);
    }

    // 3) sequential recurrence (persistent, SM-resident weights, data-flow sync)
    recurrent_kernel<<<nsm, 512, DSM_BYTES>>>(Whh, bhh, fc1w, fc1b, fc2w, fc2b, nsm);

    // 4) deferred heads: means (identity) and stds (softplus)
    {
        dim3 grid(H_DIM / 64, T_STEPS / 128);
        gemm_bias_act<<<grid, 256>>>(S, meanw, meanb, out, T_STEPS, H_DIM, H_DIM, 0);
        gemm_bias_act<<<grid, 256>>>(S, stdw,  stdb,  out + (size_t)T_STEPS * H_DIM,
                                     T_STEPS, H_DIM, H_DIM, 1);
    }
}